// round 15
// baseline (speedup 1.0000x reference)
#include <cuda_runtime.h>
#include <cuda_fp16.h>
#include <math.h>

#define N_NODES 16384
#define E_EDGES 524288
#define F_IN    128
#define H_DIM   256
#define A_DIM   64

#define CAP      128     // bucket capacity per source node (max raw degree ~57)
#define LIST_CAP 160
#define NB       128     // nodes per fused block, grid = 128

// Scratch (static __device__ globals; zero-initialized at module load)
__device__ int            g_cnt[N_NODES];          // raw out-degree (re-zeroed by k_fused)
__device__ unsigned short g_slot[N_NODES * CAP];   // bucketed dst lists (4 MB, u16 ids)
__device__ __half         g_xh[N_NODES * F_IN];    // fp16 mirror of X (4 MB)
__device__ float          g_gacc[H_DIM];           // zeroed by k_build each run
__device__ float          g_hh[H_DIM];             // head layer-1 outputs
__device__ unsigned       g_done;                  // head ticket (self-resetting)

// ---------------------------------------------------------------------------
// helpers
// ---------------------------------------------------------------------------
__device__ __forceinline__ void hacc(float4& acc, uint2 v) {
    __half2 h0 = *reinterpret_cast<__half2*>(&v.x);
    __half2 h1 = *reinterpret_cast<__half2*>(&v.y);
    float2 f0 = __half22float2(h0);
    float2 f1 = __half22float2(h1);
    acc.x += f0.x; acc.y += f0.y; acc.z += f1.x; acc.w += f1.y;
}
__device__ __forceinline__ unsigned f2tf32(float f) {
    unsigned u;
    asm("cvt.rna.tf32.f32 %0, %1;" : "=r"(u) : "f"(f));
    return u;
}
__device__ __forceinline__ void mma_tf32(float d[4],
                                         unsigned a0, unsigned a1,
                                         unsigned a2, unsigned a3,
                                         unsigned b0, unsigned b1) {
    asm volatile(
        "mma.sync.aligned.m16n8k8.row.col.f32.tf32.tf32.f32 "
        "{%0,%1,%2,%3}, {%4,%5,%6,%7}, {%8,%9}, {%0,%1,%2,%3};"
        : "+f"(d[0]), "+f"(d[1]), "+f"(d[2]), "+f"(d[3])
        : "r"(a0), "r"(a1), "r"(a2), "r"(a3), "r"(b0), "r"(b1));
}

// ---------------------------------------------------------------------------
// K1: bucket build + fp16 mirror of X + g_gacc zero. One edge per thread.
// (R9/R14-verified shape.)
// ---------------------------------------------------------------------------
__global__ void k_build(const int* __restrict__ ei, const float* __restrict__ X) {
    int e = blockIdx.x * blockDim.x + threadIdx.x;
    if (e < H_DIM) g_gacc[e] = 0.0f;
    {   // fp16 mirror: E threads x 4 elems = N*F exactly
        float4 v = ((const float4*)X)[e];
        __half2 h0 = __floats2half2_rn(v.x, v.y);
        __half2 h1 = __floats2half2_rn(v.z, v.w);
        uint2 o;
        o.x = *reinterpret_cast<unsigned*>(&h0);
        o.y = *reinterpret_cast<unsigned*>(&h1);
        ((uint2*)g_xh)[e] = o;
    }
    int s = ei[e];
    int d = ei[E_EDGES + e];
    int pos = atomicAdd(&g_cnt[s], 1);
    if (pos < CAP) g_slot[s * CAP + pos] = (unsigned short)d;
}

// ---------------------------------------------------------------------------
// K2: FUSED gather + tensor-core GEMM + relu + node-sum.
// 512 threads = 16 warps, 128 nodes/block, grid = 128 (1 wave, occ 1).
// Phase A: warp w gathers nodes w*8..w*8+7 (fp16 neighbor reads, smem-bitmap
//          dedup aliased into ws region), writes tf32 DIRECTLY into ys smem
//          (no g_y global round-trip, no separate ys-fill pass).
// Phase B: mma.sync m16n8k8 tf32 on ys x ws, bias+relu, node-sum -> g_gacc.
// smem: ys 128*132 + ws 128*264 + gpart 256 = 203,776 B
// ---------------------------------------------------------------------------
#define YS_STRIDE 132
#define WS_STRIDE 264
#define GEMM_SMEM_BYTES ((NB * YS_STRIDE + 128 * WS_STRIDE + 256) * 4)

__global__ void k_fused(const float* __restrict__ X,
                        const float* __restrict__ Wg, const float* __restrict__ bg) {
    extern __shared__ float smem[];
    float* ys    = smem;                          // [128 nodes][132] (tf32 bits)
    float* ws    = smem + NB * YS_STRIDE;         // [128 k][264] (256 h used)
    float* gpart = ws + 128 * WS_STRIDE;          // [256]

    unsigned* ysu = (unsigned*)ys;
    unsigned* wsu = (unsigned*)ws;

    int tid  = threadIdx.x;              // 512
    int lane = tid & 31;
    int warp = tid >> 5;                 // 0..15
    int node0 = blockIdx.x * NB;

    // ---- Phase A: gather (bitmap + list alias into ws region) ----
    unsigned* bitmap = ((unsigned*)ws) + warp * 512;           // 16*2KB = 32KB
    int*      list   = ((int*)ws) + 16 * 512 + warp * LIST_CAP;// +10KB (fits in ws)
    const uint2* Xh2 = (const uint2*)g_xh;

    for (int i = 0; i < NB / 16; i++) {   // 8 nodes per warp
        int n_loc = warp * (NB / 16) + i;
        int n = node0 + n_loc;

        #pragma unroll
        for (int j = lane; j < 512; j += 32) bitmap[j] = 0u;
        __syncwarp();

        int len = g_cnt[n];
        if (len > CAP) len = CAP;
        const unsigned short* row = g_slot + n * CAP;
        int cnt = 0;
        for (int b = 0; b < len; b += 32) {
            int e = b + lane;
            int isnew = 0, d = 0;
            if (e < len) {
                d = (int)row[e];
                unsigned m = 1u << (d & 31);
                unsigned old = atomicOr(&bitmap[d >> 5], m);
                isnew = ((old & m) == 0u);
            }
            unsigned bal = __ballot_sync(0xffffffffu, isnew);
            if (isnew) {
                int pos = cnt + __popc(bal & ((1u << lane) - 1u));
                if (pos < LIST_CAP) list[pos] = d;
            }
            cnt += __popc(bal);
        }
        if (cnt > LIST_CAP) cnt = LIST_CAP;
        __syncwarp();

        // acc = X[n] (exact fp32 identity) + sum_{unique d} Xh[d]; unroll 8 (MLP)
        float4 acc = ((const float4*)X)[(size_t)n * 32 + lane];
        int k = 0;
        for (; k + 8 <= cnt; k += 8) {
            uint2 v0 = Xh2[(size_t)list[k + 0] * 32 + lane];
            uint2 v1 = Xh2[(size_t)list[k + 1] * 32 + lane];
            uint2 v2 = Xh2[(size_t)list[k + 2] * 32 + lane];
            uint2 v3 = Xh2[(size_t)list[k + 3] * 32 + lane];
            uint2 v4 = Xh2[(size_t)list[k + 4] * 32 + lane];
            uint2 v5 = Xh2[(size_t)list[k + 5] * 32 + lane];
            uint2 v6 = Xh2[(size_t)list[k + 6] * 32 + lane];
            uint2 v7 = Xh2[(size_t)list[k + 7] * 32 + lane];
            hacc(acc, v0); hacc(acc, v1); hacc(acc, v2); hacc(acc, v3);
            hacc(acc, v4); hacc(acc, v5); hacc(acc, v6); hacc(acc, v7);
        }
        for (; k < cnt; k++)
            hacc(acc, Xh2[(size_t)list[k] * 32 + lane]);

        float inv = 1.0f / (float)(1 + cnt);
        // normalize + convert to tf32, write straight into the MMA A-tile
        uint4 o = make_uint4(f2tf32(acc.x * inv), f2tf32(acc.y * inv),
                             f2tf32(acc.z * inv), f2tf32(acc.w * inv));
        *((uint4*)(ysu + n_loc * YS_STRIDE + lane * 4)) = o;
    }

    __syncthreads();                     // all warps done with bitmap/list + ys
    if (tid < NB) g_cnt[node0 + tid] = 0;   // restore invariant for next replay

    // ---- Phase B: W fill (overwrites bitmap/list) + MMA ----
    for (int idx = tid; idx < 256 * 32; idx += 512) {
        int h  = idx & 255;
        int k4 = idx >> 8;
        float4 w = ((const float4*)(Wg + (size_t)h * F_IN))[k4];
        wsu[(k4 * 4 + 0) * WS_STRIDE + h] = f2tf32(w.x);
        wsu[(k4 * 4 + 1) * WS_STRIDE + h] = f2tf32(w.y);
        wsu[(k4 * 4 + 2) * WS_STRIDE + h] = f2tf32(w.z);
        wsu[(k4 * 4 + 3) * WS_STRIDE + h] = f2tf32(w.w);
    }
    if (tid < 256) gpart[tid] = 0.0f;
    __syncthreads();

    int g  = lane >> 2;
    int t4 = lane & 3;
    int mt = warp & 3;
    int nt = warp >> 2;
    int ntb = nt * 64;

    float d[2][8][4];
    #pragma unroll
    for (int mi = 0; mi < 2; mi++)
        #pragma unroll
        for (int j = 0; j < 8; j++)
            #pragma unroll
            for (int q = 0; q < 4; q++) d[mi][j][q] = 0.0f;

    #pragma unroll 4
    for (int ks = 0; ks < 16; ks++) {
        int k0 = ks * 8;
        unsigned a[2][4];
        #pragma unroll
        for (int mi = 0; mi < 2; mi++) {
            int row = mt * 32 + mi * 16 + g;
            a[mi][0] = ysu[(row)     * YS_STRIDE + k0 + t4];
            a[mi][1] = ysu[(row + 8) * YS_STRIDE + k0 + t4];
            a[mi][2] = ysu[(row)     * YS_STRIDE + k0 + t4 + 4];
            a[mi][3] = ysu[(row + 8) * YS_STRIDE + k0 + t4 + 4];
        }
        #pragma unroll
        for (int j = 0; j < 8; j++) {
            unsigned b0 = wsu[(k0 + t4)     * WS_STRIDE + ntb + j * 8 + g];
            unsigned b1 = wsu[(k0 + t4 + 4) * WS_STRIDE + ntb + j * 8 + g];
            mma_tf32(d[0][j], a[0][0], a[0][1], a[0][2], a[0][3], b0, b1);
            mma_tf32(d[1][j], a[1][0], a[1][1], a[1][2], a[1][3], b0, b1);
        }
    }

    #pragma unroll
    for (int j = 0; j < 8; j++) {
        int h0 = ntb + j * 8 + 2 * t4;
        float bias0 = bg[h0];
        float bias1 = bg[h0 + 1];
        float s0 = 0.0f, s1 = 0.0f;
        #pragma unroll
        for (int mi = 0; mi < 2; mi++) {
            s0 += fmaxf(d[mi][j][0] + bias0, 0.0f) + fmaxf(d[mi][j][2] + bias0, 0.0f);
            s1 += fmaxf(d[mi][j][1] + bias1, 0.0f) + fmaxf(d[mi][j][3] + bias1, 0.0f);
        }
        #pragma unroll
        for (int off = 16; off >= 4; off >>= 1) {
            s0 += __shfl_down_sync(0xffffffffu, s0, off);
            s1 += __shfl_down_sync(0xffffffffu, s1, off);
        }
        if (lane < 4) {
            atomicAdd(&gpart[ntb + j * 8 + 2 * lane],     s0);
            atomicAdd(&gpart[ntb + j * 8 + 2 * lane + 1], s1);
        }
    }
    __syncthreads();
    if (tid < 256) atomicAdd(&g_gacc[tid], gpart[tid]);
}

// ---------------------------------------------------------------------------
// K3: head. 32 blocks x 256 threads; coalesced warp-per-output layer 1;
// last block (fence+ticket) does layer 2 + softmax + value. (R12-verified.)
// ---------------------------------------------------------------------------
__global__ void k_head(const float* __restrict__ Wa1, const float* __restrict__ ba1,
                       const float* __restrict__ Wa2, const float* __restrict__ ba2,
                       const float* __restrict__ Wc1, const float* __restrict__ bc1,
                       const float* __restrict__ Wc2, const float* __restrict__ bc2,
                       float* __restrict__ out) {
    int tid  = threadIdx.x;          // 256
    int lane = tid & 31;
    int warp = tid >> 5;             // 0..7

    {
        int o = blockIdx.x * 8 + warp;
        const float* Wrow = (o < 128) ? (Wa1 + (size_t)o * H_DIM)
                                      : (Wc1 + (size_t)(o - 128) * H_DIM);
        float bias = (o < 128) ? ba1[o] : bc1[o - 128];
        float s = 0.0f;
        #pragma unroll
        for (int j = 0; j < 8; j++) {
            int k = lane + j * 32;
            s += g_gacc[k] * Wrow[k];
        }
        #pragma unroll
        for (int off = 16; off > 0; off >>= 1)
            s += __shfl_down_sync(0xffffffffu, s, off);
        if (lane == 0)
            g_hh[o] = fmaxf(s * (1.0f / (float)N_NODES) + bias, 0.0f);
    }

    __threadfence();
    __syncthreads();
    __shared__ unsigned s_ticket;
    if (tid == 0) s_ticket = atomicAdd(&g_done, 1u);
    __syncthreads();
    if (s_ticket != gridDim.x - 1) return;
    if (tid == 0) g_done = 0;        // reset for next graph replay

    __shared__ float hh[H_DIM];
    __shared__ float lgs[A_DIM + 1];
    hh[tid] = g_hh[tid];
    __syncthreads();

    #pragma unroll
    for (int q = 0; q < 8; q++) {
        int o = warp * 8 + q;        // 0..63
        const float* Wrow = Wa2 + (size_t)o * (H_DIM / 2);
        float s = 0.0f;
        #pragma unroll
        for (int j = 0; j < 4; j++)
            s += hh[lane + j * 32] * Wrow[lane + j * 32];
        #pragma unroll
        for (int off = 16; off > 0; off >>= 1)
            s += __shfl_down_sync(0xffffffffu, s, off);
        if (lane == 0) lgs[o] = s + ba2[o];
    }
    if (warp == 0) {
        float s = 0.0f;
        #pragma unroll
        for (int j = 0; j < 4; j++)
            s += hh[128 + lane + j * 32] * Wc2[lane + j * 32];
        #pragma unroll
        for (int off = 16; off > 0; off >>= 1)
            s += __shfl_down_sync(0xffffffffu, s, off);
        if (lane == 0) lgs[A_DIM] = s + bc2[0];
    }
    __syncthreads();

    if (warp == 0) {
        float a = lgs[lane], b = lgs[lane + 32];
        float m = fmaxf(a, b);
        #pragma unroll
        for (int off = 16; off > 0; off >>= 1)
            m = fmaxf(m, __shfl_xor_sync(0xffffffffu, m, off));
        float ea = expf(a - m), eb = expf(b - m);
        float s = ea + eb;
        #pragma unroll
        for (int off = 16; off > 0; off >>= 1)
            s += __shfl_xor_sync(0xffffffffu, s, off);
        float inv = 1.0f / s;
        out[lane] = ea * inv;
        out[lane + 32] = eb * inv;
        if (lane == 0) out[A_DIM] = lgs[A_DIM];
    }
}

// ---------------------------------------------------------------------------
extern "C" void kernel_launch(void* const* d_in, const int* in_sizes, int n_in,
                              void* d_out, int out_size) {
    const float* X   = (const float*)d_in[0];
    const int*   ei  = (const int*)  d_in[1];
    const float* Wg  = (const float*)d_in[2];
    const float* bg  = (const float*)d_in[3];
    const float* Wa1 = (const float*)d_in[4];
    const float* ba1 = (const float*)d_in[5];
    const float* Wa2 = (const float*)d_in[6];
    const float* ba2 = (const float*)d_in[7];
    const float* Wc1 = (const float*)d_in[8];
    const float* bc1 = (const float*)d_in[9];
    const float* Wc2 = (const float*)d_in[10];
    const float* bc2 = (const float*)d_in[11];
    float* out = (float*)d_out;

    cudaFuncSetAttribute(k_fused, cudaFuncAttributeMaxDynamicSharedMemorySize,
                         GEMM_SMEM_BYTES);

    k_build<<<E_EDGES / 256, 256>>>(ei, X);
    k_fused<<<N_NODES / NB, 512, GEMM_SMEM_BYTES>>>(X, Wg, bg);
    k_head<<<32, 256>>>(Wa1, ba1, Wa2, ba2, Wc1, bc1, Wc2, bc2, out);
}

// round 16
// speedup vs baseline: 1.2278x; 1.2278x over previous
#include <cuda_runtime.h>
#include <cuda_fp16.h>
#include <math.h>

#define N_NODES 16384
#define E_EDGES 524288
#define F_IN    128
#define H_DIM   256
#define A_DIM   64

#define CAP      128     // bucket capacity per source node (max raw degree ~57)
#define LIST_CAP 160
#define GW       16      // warps (nodes) per gather block
#define NB       128     // nodes per gemm block

// Scratch (static __device__ globals; zero-initialized at module load)
__device__ int            g_cnt[N_NODES];          // raw out-degree (re-zeroed by k_gather)
__device__ unsigned short g_slot[N_NODES * CAP];   // bucketed dst lists (4 MB, u16 ids)
__device__ __half         g_xh[N_NODES * F_IN];    // fp16 mirror of X (4 MB)
__device__ float          g_y[N_NODES * F_IN];     // normalized aggregated features (8 MB)
__device__ float          g_gacc[H_DIM];           // zeroed by k_build each run
__device__ float          g_hh[H_DIM];             // head layer-1 outputs
__device__ unsigned       g_done;                  // head ticket (self-resetting)

// ---------------------------------------------------------------------------
// helpers
// ---------------------------------------------------------------------------
__device__ __forceinline__ void hacc(float4& acc, uint2 v) {
    __half2 h0 = *reinterpret_cast<__half2*>(&v.x);
    __half2 h1 = *reinterpret_cast<__half2*>(&v.y);
    float2 f0 = __half22float2(h0);
    float2 f1 = __half22float2(h1);
    acc.x += f0.x; acc.y += f0.y; acc.z += f1.x; acc.w += f1.y;
}
__device__ __forceinline__ unsigned f2tf32(float f) {
    unsigned u;
    asm("cvt.rna.tf32.f32 %0, %1;" : "=r"(u) : "f"(f));
    return u;
}
__device__ __forceinline__ void mma_tf32(float d[4],
                                         unsigned a0, unsigned a1,
                                         unsigned a2, unsigned a3,
                                         unsigned b0, unsigned b1) {
    asm volatile(
        "mma.sync.aligned.m16n8k8.row.col.f32.tf32.tf32.f32 "
        "{%0,%1,%2,%3}, {%4,%5,%6,%7}, {%8,%9}, {%0,%1,%2,%3};"
        : "+f"(d[0]), "+f"(d[1]), "+f"(d[2]), "+f"(d[3])
        : "r"(a0), "r"(a1), "r"(a2), "r"(a3), "r"(b0), "r"(b1));
}

// ---------------------------------------------------------------------------
// K1: bucket build + fp16 mirror of X + g_gacc zero. One edge per thread.
// (R9/R14-verified shape.) Triggers PDL for k_gather at the end.
// ---------------------------------------------------------------------------
__global__ void k_build(const int* __restrict__ ei, const float* __restrict__ X) {
    int e = blockIdx.x * blockDim.x + threadIdx.x;
    if (e < H_DIM) g_gacc[e] = 0.0f;
    {   // fp16 mirror: E threads x 4 elems = N*F exactly
        float4 v = ((const float4*)X)[e];
        __half2 h0 = __floats2half2_rn(v.x, v.y);
        __half2 h1 = __floats2half2_rn(v.z, v.w);
        uint2 o;
        o.x = *reinterpret_cast<unsigned*>(&h0);
        o.y = *reinterpret_cast<unsigned*>(&h1);
        ((uint2*)g_xh)[e] = o;
    }
    int s = ei[e];
    int d = ei[E_EDGES + e];
    int pos = atomicAdd(&g_cnt[s], 1);
    if (pos < CAP) g_slot[s * CAP + pos] = (unsigned short)d;
    cudaTriggerProgrammaticLaunchCompletion();
}

// ---------------------------------------------------------------------------
// K2: gather. One warp per node, fp16 neighbor reads, fp32 identity + accum.
// PDL: prelude (bitmap zero) runs before the dependency sync, overlapping
// k_build's tail; body reads g_cnt/g_slot/g_xh only after the sync.
// ---------------------------------------------------------------------------
__global__ __launch_bounds__(GW * 32, 4)
void k_gather(const float* __restrict__ X) {
    __shared__ unsigned bitmap_s[GW * 512];
    __shared__ int      list_s[GW * LIST_CAP];

    int lane = threadIdx.x & 31;
    int warp = threadIdx.x >> 5;
    int n = blockIdx.x * GW + warp;

    unsigned* bitmap = bitmap_s + warp * 512;
    int*      list   = list_s + warp * LIST_CAP;
    const uint2* Xh2 = (const uint2*)g_xh;

    // prelude: zero bitmap + load identity row (X is an input, not produced
    // by k_build) — overlaps the predecessor's tail
    #pragma unroll
    for (int j = lane; j < 512; j += 32) bitmap[j] = 0u;
    float4 acc = ((const float4*)X)[(size_t)n * 32 + lane];
    __syncwarp();

    cudaGridDependencySynchronize();   // wait for k_build's writes

    int len = g_cnt[n];
    if (len > CAP) len = CAP;
    const unsigned short* row = g_slot + n * CAP;
    int cnt = 0;
    for (int b = 0; b < len; b += 32) {
        int e = b + lane;
        int isnew = 0, d = 0;
        if (e < len) {
            d = (int)row[e];
            unsigned m = 1u << (d & 31);
            unsigned old = atomicOr(&bitmap[d >> 5], m);
            isnew = ((old & m) == 0u);
        }
        unsigned bal = __ballot_sync(0xffffffffu, isnew);
        if (isnew) {
            int pos = cnt + __popc(bal & ((1u << lane) - 1u));
            if (pos < LIST_CAP) list[pos] = d;
        }
        cnt += __popc(bal);
    }
    if (cnt > LIST_CAP) cnt = LIST_CAP;
    __syncwarp();

    int k = 0;
    for (; k + 8 <= cnt; k += 8) {
        uint2 v0 = Xh2[(size_t)list[k + 0] * 32 + lane];
        uint2 v1 = Xh2[(size_t)list[k + 1] * 32 + lane];
        uint2 v2 = Xh2[(size_t)list[k + 2] * 32 + lane];
        uint2 v3 = Xh2[(size_t)list[k + 3] * 32 + lane];
        uint2 v4 = Xh2[(size_t)list[k + 4] * 32 + lane];
        uint2 v5 = Xh2[(size_t)list[k + 5] * 32 + lane];
        uint2 v6 = Xh2[(size_t)list[k + 6] * 32 + lane];
        uint2 v7 = Xh2[(size_t)list[k + 7] * 32 + lane];
        hacc(acc, v0); hacc(acc, v1); hacc(acc, v2); hacc(acc, v3);
        hacc(acc, v4); hacc(acc, v5); hacc(acc, v6); hacc(acc, v7);
    }
    for (; k < cnt; k++)
        hacc(acc, Xh2[(size_t)list[k] * 32 + lane]);

    float inv = 1.0f / (float)(1 + cnt);
    acc.x *= inv; acc.y *= inv; acc.z *= inv; acc.w *= inv;
    ((float4*)(g_y + (size_t)n * F_IN))[lane] = acc;

    if (lane == 0) g_cnt[n] = 0;
    cudaTriggerProgrammaticLaunchCompletion();
}

// ---------------------------------------------------------------------------
// K3: tensor-core GEMM (mma.sync m16n8k8 tf32) + relu + node-sum.
// PDL: prelude (W-tile smem fill + gpart zero, depends only on Wg) overlaps
// k_gather's tail; ys fill (reads g_y) happens after the dependency sync.
// ---------------------------------------------------------------------------
#define YS_STRIDE 132
#define WS_STRIDE 264
#define GEMM_SMEM_BYTES ((NB * YS_STRIDE + 128 * WS_STRIDE + 256) * 4)

__global__ void k_gemm(const float* __restrict__ Wg, const float* __restrict__ bg) {
    extern __shared__ float smem[];
    float* ys    = smem;                          // [128 nodes][132]
    float* ws    = smem + NB * YS_STRIDE;         // [128 k][264] (256 h used)
    float* gpart = ws + 128 * WS_STRIDE;          // [256]

    unsigned* ysu = (unsigned*)ys;
    unsigned* wsu = (unsigned*)ws;

    int tid  = threadIdx.x;              // 512
    int lane = tid & 31;
    int warp = tid >> 5;                 // 0..15
    int node0 = blockIdx.x * NB;

    int g  = lane >> 2;
    int t4 = lane & 3;
    int mt = warp & 3;
    int nt = warp >> 2;
    int ntb = nt * 64;

    // prelude: W half -> smem (independent of k_gather), gpart zero
    if (tid < 256) gpart[tid] = 0.0f;
    for (int idx = tid; idx < 256 * 32; idx += 512) {
        int h  = idx & 255;
        int k4 = idx >> 8;
        float4 w = ((const float4*)(Wg + (size_t)h * F_IN))[k4];
        wsu[(k4 * 4 + 0) * WS_STRIDE + h] = f2tf32(w.x);
        wsu[(k4 * 4 + 1) * WS_STRIDE + h] = f2tf32(w.y);
        wsu[(k4 * 4 + 2) * WS_STRIDE + h] = f2tf32(w.z);
        wsu[(k4 * 4 + 3) * WS_STRIDE + h] = f2tf32(w.w);
    }

    cudaGridDependencySynchronize();     // wait for k_gather's g_y

    const float4* Y4 = (const float4*)g_y;
    for (int idx = tid; idx < NB * 32; idx += 512) {
        int r  = idx >> 5;
        int k4 = idx & 31;
        float4 v = Y4[(size_t)(node0 + r) * 32 + k4];
        uint4 o = make_uint4(f2tf32(v.x), f2tf32(v.y), f2tf32(v.z), f2tf32(v.w));
        *((uint4*)(ysu + r * YS_STRIDE + k4 * 4)) = o;
    }
    __syncthreads();

    float d[2][8][4];
    #pragma unroll
    for (int mi = 0; mi < 2; mi++)
        #pragma unroll
        for (int j = 0; j < 8; j++)
            #pragma unroll
            for (int q = 0; q < 4; q++) d[mi][j][q] = 0.0f;

    #pragma unroll 4
    for (int ks = 0; ks < 16; ks++) {
        int k0 = ks * 8;
        unsigned a[2][4];
        #pragma unroll
        for (int mi = 0; mi < 2; mi++) {
            int row = mt * 32 + mi * 16 + g;
            a[mi][0] = ysu[(row)     * YS_STRIDE + k0 + t4];
            a[mi][1] = ysu[(row + 8) * YS_STRIDE + k0 + t4];
            a[mi][2] = ysu[(row)     * YS_STRIDE + k0 + t4 + 4];
            a[mi][3] = ysu[(row + 8) * YS_STRIDE + k0 + t4 + 4];
        }
        #pragma unroll
        for (int j = 0; j < 8; j++) {
            unsigned b0 = wsu[(k0 + t4)     * WS_STRIDE + ntb + j * 8 + g];
            unsigned b1 = wsu[(k0 + t4 + 4) * WS_STRIDE + ntb + j * 8 + g];
            mma_tf32(d[0][j], a[0][0], a[0][1], a[0][2], a[0][3], b0, b1);
            mma_tf32(d[1][j], a[1][0], a[1][1], a[1][2], a[1][3], b0, b1);
        }
    }

    #pragma unroll
    for (int j = 0; j < 8; j++) {
        int h0 = ntb + j * 8 + 2 * t4;
        float bias0 = bg[h0];
        float bias1 = bg[h0 + 1];
        float s0 = 0.0f, s1 = 0.0f;
        #pragma unroll
        for (int mi = 0; mi < 2; mi++) {
            s0 += fmaxf(d[mi][j][0] + bias0, 0.0f) + fmaxf(d[mi][j][2] + bias0, 0.0f);
            s1 += fmaxf(d[mi][j][1] + bias1, 0.0f) + fmaxf(d[mi][j][3] + bias1, 0.0f);
        }
        #pragma unroll
        for (int off = 16; off >= 4; off >>= 1) {
            s0 += __shfl_down_sync(0xffffffffu, s0, off);
            s1 += __shfl_down_sync(0xffffffffu, s1, off);
        }
        if (lane < 4) {
            atomicAdd(&gpart[ntb + j * 8 + 2 * lane],     s0);
            atomicAdd(&gpart[ntb + j * 8 + 2 * lane + 1], s1);
        }
    }
    __syncthreads();
    if (tid < 256) atomicAdd(&g_gacc[tid], gpart[tid]);
    cudaTriggerProgrammaticLaunchCompletion();
}

// ---------------------------------------------------------------------------
// K4: head. 32 blocks x 256 threads; coalesced warp-per-output layer 1.
// PDL: layer-1 WEIGHTS are preloaded into registers BEFORE the dependency
// sync (cold-DRAM fetch overlaps k_gemm); after sync g_gacc is an L2 hit.
// Last block (fence+ticket) does layer 2 + softmax + value.
// ---------------------------------------------------------------------------
__global__ void k_head(const float* __restrict__ Wa1, const float* __restrict__ ba1,
                       const float* __restrict__ Wa2, const float* __restrict__ ba2,
                       const float* __restrict__ Wc1, const float* __restrict__ bc1,
                       const float* __restrict__ Wc2, const float* __restrict__ bc2,
                       float* __restrict__ out) {
    int tid  = threadIdx.x;          // 256
    int lane = tid & 31;
    int warp = tid >> 5;             // 0..7

    // prelude: fetch layer-1 weights + bias (independent of k_gemm output)
    int o = blockIdx.x * 8 + warp;
    const float* Wrow = (o < 128) ? (Wa1 + (size_t)o * H_DIM)
                                  : (Wc1 + (size_t)(o - 128) * H_DIM);
    float bias = (o < 128) ? ba1[o] : bc1[o - 128];
    float w[8];
    #pragma unroll
    for (int j = 0; j < 8; j++)
        w[j] = Wrow[lane + j * 32];

    cudaGridDependencySynchronize();   // wait for k_gemm's g_gacc

    {
        float s = 0.0f;
        #pragma unroll
        for (int j = 0; j < 8; j++)
            s += g_gacc[lane + j * 32] * w[j];
        #pragma unroll
        for (int off = 16; off > 0; off >>= 1)
            s += __shfl_down_sync(0xffffffffu, s, off);
        if (lane == 0)
            g_hh[o] = fmaxf(s * (1.0f / (float)N_NODES) + bias, 0.0f);
    }

    __threadfence();
    __syncthreads();
    __shared__ unsigned s_ticket;
    if (tid == 0) s_ticket = atomicAdd(&g_done, 1u);
    __syncthreads();
    if (s_ticket != gridDim.x - 1) return;
    if (tid == 0) g_done = 0;        // reset for next graph replay

    __shared__ float hh[H_DIM];
    __shared__ float lgs[A_DIM + 1];
    hh[tid] = g_hh[tid];
    __syncthreads();

    #pragma unroll
    for (int q = 0; q < 8; q++) {
        int oo = warp * 8 + q;       // 0..63
        const float* W2 = Wa2 + (size_t)oo * (H_DIM / 2);
        float s = 0.0f;
        #pragma unroll
        for (int j = 0; j < 4; j++)
            s += hh[lane + j * 32] * W2[lane + j * 32];
        #pragma unroll
        for (int off = 16; off > 0; off >>= 1)
            s += __shfl_down_sync(0xffffffffu, s, off);
        if (lane == 0) lgs[oo] = s + ba2[oo];
    }
    if (warp == 0) {
        float s = 0.0f;
        #pragma unroll
        for (int j = 0; j < 4; j++)
            s += hh[128 + lane + j * 32] * Wc2[lane + j * 32];
        #pragma unroll
        for (int off = 16; off > 0; off >>= 1)
            s += __shfl_down_sync(0xffffffffu, s, off);
        if (lane == 0) lgs[A_DIM] = s + bc2[0];
    }
    __syncthreads();

    if (warp == 0) {
        float a = lgs[lane], b = lgs[lane + 32];
        float m = fmaxf(a, b);
        #pragma unroll
        for (int off = 16; off > 0; off >>= 1)
            m = fmaxf(m, __shfl_xor_sync(0xffffffffu, m, off));
        float ea = expf(a - m), eb = expf(b - m);
        float s = ea + eb;
        #pragma unroll
        for (int off = 16; off > 0; off >>= 1)
            s += __shfl_xor_sync(0xffffffffu, s, off);
        float inv = 1.0f / s;
        out[lane] = ea * inv;
        out[lane + 32] = eb * inv;
        if (lane == 0) out[A_DIM] = lgs[A_DIM];
    }
}

// ---------------------------------------------------------------------------
extern "C" void kernel_launch(void* const* d_in, const int* in_sizes, int n_in,
                              void* d_out, int out_size) {
    const float* X   = (const float*)d_in[0];
    const int*   ei  = (const int*)  d_in[1];
    const float* Wg  = (const float*)d_in[2];
    const float* bg  = (const float*)d_in[3];
    const float* Wa1 = (const float*)d_in[4];
    const float* ba1 = (const float*)d_in[5];
    const float* Wa2 = (const float*)d_in[6];
    const float* ba2 = (const float*)d_in[7];
    const float* Wc1 = (const float*)d_in[8];
    const float* bc1 = (const float*)d_in[9];
    const float* Wc2 = (const float*)d_in[10];
    const float* bc2 = (const float*)d_in[11];
    float* out = (float*)d_out;

    cudaFuncSetAttribute(k_gemm, cudaFuncAttributeMaxDynamicSharedMemorySize,
                         GEMM_SMEM_BYTES);

    // PDL attribute: dependent kernels may begin (and run their preludes)
    // while the predecessor drains; correctness enforced by
    // cudaGridDependencySynchronize() inside each dependent kernel.
    cudaLaunchAttribute attr[1];
    attr[0].id = cudaLaunchAttributeProgrammaticStreamSerialization;
    attr[0].val.programmaticStreamSerializationAllowed = 1;

    // K1: normal launch
    k_build<<<E_EDGES / 256, 256>>>(ei, X);

    // K2: PDL launch
    {
        cudaLaunchConfig_t cfg = {};
        cfg.gridDim = dim3(N_NODES / GW);
        cfg.blockDim = dim3(GW * 32);
        cfg.dynamicSmemBytes = 0;
        cfg.stream = 0;
        cfg.attrs = attr;
        cfg.numAttrs = 1;
        cudaLaunchKernelEx(&cfg, k_gather, X);
    }
    // K3: PDL launch
    {
        cudaLaunchConfig_t cfg = {};
        cfg.gridDim = dim3(N_NODES / NB);
        cfg.blockDim = dim3(512);
        cfg.dynamicSmemBytes = GEMM_SMEM_BYTES;
        cfg.stream = 0;
        cfg.attrs = attr;
        cfg.numAttrs = 1;
        cudaLaunchKernelEx(&cfg, k_gemm, Wg, bg);
    }
    // K4: PDL launch
    {
        cudaLaunchConfig_t cfg = {};
        cfg.gridDim = dim3(32);
        cfg.blockDim = dim3(256);
        cfg.dynamicSmemBytes = 0;
        cfg.stream = 0;
        cfg.attrs = attr;
        cfg.numAttrs = 1;
        cudaLaunchKernelEx(&cfg, k_head, Wa1, ba1, Wa2, ba2, Wc1, bc1, Wc2, bc2, out);
    }
}